// round 10
// baseline (speedup 1.0000x reference)
#include <cuda_runtime.h>
#include <cuda_fp16.h>
#include <cuda_bf16.h>
#include <math.h>
#include <float.h>

#define NB 144          // total blocks (1 CTA/SM, 144 <= 148)
#define GROUPS 4        // independent groups
#define GNB 36          // blocks per group
#define SPG 8           // timesteps per group
#define NT 1024         // threads per block
#define N_ 4096
#define S_ 32
#define D_ 128
#define MAXP 4352       // worst-case padded dim bound (multiple of 256)
#define ITS 20
#define EPSK 1e-6f
#define SMEM_BYTES 73728   // 4 tiles x 128 rows x 72 halves x 2B

// ---------------- persistent scratch (__device__ globals: allocation-free) ----------------
__device__ __align__(16) __nv_bfloat16 g_Xh[(size_t)S_ * N_ * D_];   // hi part of permuted X
__device__ __align__(16) __nv_bfloat16 g_Xl[(size_t)S_ * N_ * D_];   // lo part
__device__ float  g_nrm[S_ * N_];
__device__ __align__(16) float  g_M [(size_t)GROUPS * MAXP * MAXP];
__device__ __align__(16) __half g_K [(size_t)GROUPS * MAXP * MAXP];
__device__ __align__(16) __half g_KT[(size_t)GROUPS * MAXP * MAXP];
__device__ __align__(16) float  g_u [GROUPS][MAXP];
__device__ __align__(16) float  g_bv[GROUPS][MAXP];
__device__ int    g_perm[GROUPS][N_];
__device__ int    g_ntA [GROUPS];
__device__ float  g_pA  [GROUPS];
__device__ float  g_pmax[GROUPS][GNB];
__device__ double g_psum[GROUPS][GNB];
__device__ double g_pres[GROUPS][GNB];
__device__ double g_res [S_];
__device__ unsigned long long g_barCnt[GROUPS * 16];
__device__ unsigned long long g_doneCnt;

// ---------------- group barrier: monotonic 64-bit counter ----------------
__device__ __forceinline__ void gbar_sync(unsigned long long* cnt, unsigned long long tgt) {
    __syncthreads();
    if (threadIdx.x == 0) {
        __threadfence();
        atomicAdd(cnt, 1ULL);
        while (*(volatile unsigned long long*)cnt < tgt) { __nanosleep(32); }
        __threadfence();
    }
    __syncthreads();
}
#define GBAR() do { ++barK; gbar_sync(cntp, barBase + (unsigned long long)barK * GNB); } while (0)

// ---------------- FFMA-only expf ----------------
__device__ __forceinline__ float fast_exp(float x) {
    const float L2E = 1.4426950408889634f;
    float y = fmaf(x, L2E, 12582912.0f);
    int   n = __float_as_int(y) - 0x4B400000;
    float r = y - 12582912.0f;
    float f = fmaf(x, L2E, -r);
    float p =        1.540353040e-4f;
    p = fmaf(p, f,   1.333355815e-3f);
    p = fmaf(p, f,   9.618129107e-3f);
    p = fmaf(p, f,   5.550410866e-2f);
    p = fmaf(p, f,   2.402265070e-1f);
    p = fmaf(p, f,   6.931471806e-1f);
    p = fmaf(p, f,   1.0f);
    return p * __int_as_float((n + 127) << 23);
}

__device__ __forceinline__ float warpMaxF(float v) {
    #pragma unroll
    for (int o = 16; o; o >>= 1) v = fmaxf(v, __shfl_down_sync(0xffffffffu, v, o));
    return v;
}
__device__ __forceinline__ float warpSumF(float v) {
    #pragma unroll
    for (int o = 16; o; o >>= 1) v += __shfl_down_sync(0xffffffffu, v, o);
    return v;
}
__device__ __forceinline__ double warpSumD(double v) {
    #pragma unroll
    for (int o = 16; o; o >>= 1) v += __shfl_down_sync(0xffffffffu, v, o);
    return v;
}
__device__ __forceinline__ void warpSum4F(float& v0, float& v1, float& v2, float& v3) {
    #pragma unroll
    for (int o = 16; o; o >>= 1) {
        v0 += __shfl_down_sync(0xffffffffu, v0, o);
        v1 += __shfl_down_sync(0xffffffffu, v1, o);
        v2 += __shfl_down_sync(0xffffffffu, v2, o);
        v3 += __shfl_down_sync(0xffffffffu, v3, o);
    }
}

// ---------------- mma.sync m16n8k16 bf16 (fp32 accum) ----------------
__device__ __forceinline__ void mma16816(float& c0, float& c1, float& c2, float& c3,
                                         unsigned a0, unsigned a1, unsigned a2, unsigned a3,
                                         unsigned b0, unsigned b1) {
    asm volatile("mma.sync.aligned.m16n8k16.row.col.f32.bf16.bf16.f32 "
        "{%0,%1,%2,%3}, {%4,%5,%6,%7}, {%8,%9}, {%0,%1,%2,%3};"
        : "+f"(c0), "+f"(c1), "+f"(c2), "+f"(c3)
        : "r"(a0), "r"(a1), "r"(a2), "r"(a3), "r"(b0), "r"(b1));
}

#define LDH 72   // padded smem row stride in halves (144B: conflict-free frag loads)

// 4-row fp16 matvec dot against smem-staged vector (segment-permuted layout)
__device__ __forceinline__ void dot4rows(const __half* base, size_t stride, int rb,
                                         const float* shv, int nseg, int lane,
                                         float& s0, float& s1, float& s2, float& s3) {
    const uint4* Kr0 = (const uint4*)(base + (size_t)(rb + 0) * stride);
    const uint4* Kr1 = (const uint4*)(base + (size_t)(rb + 1) * stride);
    const uint4* Kr2 = (const uint4*)(base + (size_t)(rb + 2) * stride);
    const uint4* Kr3 = (const uint4*)(base + (size_t)(rb + 3) * stride);
    float a0 = 0, a1 = 0, a2 = 0, a3 = 0;
    float b0 = 0, b1 = 0, b2 = 0, b3 = 0;
    for (int sg = 0; sg < nseg; sg++) {
        uint4 k0 = __ldcg(Kr0 + sg * 32 + lane);
        uint4 k1 = __ldcg(Kr1 + sg * 32 + lane);
        uint4 k2 = __ldcg(Kr2 + sg * 32 + lane);
        uint4 k3 = __ldcg(Kr3 + sg * 32 + lane);
        float4 u0 = *(const float4*)(shv + sg * 256 + lane * 4);
        float4 u1 = *(const float4*)(shv + sg * 256 + 128 + lane * 4);
        {
            const __half2* h = (const __half2*)&k0;
            float2 p0 = __half22float2(h[0]), p1 = __half22float2(h[1]);
            float2 p2 = __half22float2(h[2]), p3 = __half22float2(h[3]);
            a0 = fmaf(p0.x, u0.x, a0); b0 = fmaf(p0.y, u0.y, b0);
            a0 = fmaf(p1.x, u0.z, a0); b0 = fmaf(p1.y, u0.w, b0);
            a0 = fmaf(p2.x, u1.x, a0); b0 = fmaf(p2.y, u1.y, b0);
            a0 = fmaf(p3.x, u1.z, a0); b0 = fmaf(p3.y, u1.w, b0);
        }
        {
            const __half2* h = (const __half2*)&k1;
            float2 p0 = __half22float2(h[0]), p1 = __half22float2(h[1]);
            float2 p2 = __half22float2(h[2]), p3 = __half22float2(h[3]);
            a1 = fmaf(p0.x, u0.x, a1); b1 = fmaf(p0.y, u0.y, b1);
            a1 = fmaf(p1.x, u0.z, a1); b1 = fmaf(p1.y, u0.w, b1);
            a1 = fmaf(p2.x, u1.x, a1); b1 = fmaf(p2.y, u1.y, b1);
            a1 = fmaf(p3.x, u1.z, a1); b1 = fmaf(p3.y, u1.w, b1);
        }
        {
            const __half2* h = (const __half2*)&k2;
            float2 p0 = __half22float2(h[0]), p1 = __half22float2(h[1]);
            float2 p2 = __half22float2(h[2]), p3 = __half22float2(h[3]);
            a2 = fmaf(p0.x, u0.x, a2); b2 = fmaf(p0.y, u0.y, b2);
            a2 = fmaf(p1.x, u0.z, a2); b2 = fmaf(p1.y, u0.w, b2);
            a2 = fmaf(p2.x, u1.x, a2); b2 = fmaf(p2.y, u1.y, b2);
            a2 = fmaf(p3.x, u1.z, a2); b2 = fmaf(p3.y, u1.w, b2);
        }
        {
            const __half2* h = (const __half2*)&k3;
            float2 p0 = __half22float2(h[0]), p1 = __half22float2(h[1]);
            float2 p2 = __half22float2(h[2]), p3 = __half22float2(h[3]);
            a3 = fmaf(p0.x, u0.x, a3); b3 = fmaf(p0.y, u0.y, b3);
            a3 = fmaf(p1.x, u0.z, a3); b3 = fmaf(p1.y, u0.w, b3);
            a3 = fmaf(p2.x, u1.x, a3); b3 = fmaf(p2.y, u1.y, b3);
            a3 = fmaf(p3.x, u1.z, a3); b3 = fmaf(p3.y, u1.w, b3);
        }
    }
    s0 = a0 + b0; s1 = a1 + b1; s2 = a2 + b2; s3 = a3 + b3;
    warpSum4F(s0, s1, s2, s3);
}

__global__ void __launch_bounds__(NT, 1)
sinkhorn_all(const float* __restrict__ X, const int* __restrict__ T, float* __restrict__ out)
{
    extern __shared__ __align__(16) char smraw[];
    float* sh = (float*)smraw;
    __nv_bfloat16* Ah = (__nv_bfloat16*)smraw;          // 128 x LDH
    __nv_bfloat16* Al = Ah + 128 * LDH;
    __nv_bfloat16* Bh = Al + 128 * LDH;
    __nv_bfloat16* Bl = Bh + 128 * LDH;

    __shared__ float  s_f[32];
    __shared__ double s_d[32];
    __shared__ float  s_delta, s_efflam;

    const int tid  = threadIdx.x;
    const int bid  = blockIdx.x;
    const int lane = tid & 31;
    const int wid  = tid >> 5;
    const int grp  = bid / GNB;
    const int lb   = bid - grp * GNB;
    const int gw   = lb * 32 + wid;        // warp within group
    const int GW   = GNB * 32;
    const int jid  = wid * GNB + lb;       // job id: spreads low-j jobs across blocks

    unsigned long long* cntp = &g_barCnt[grp * 16];
    unsigned long long v0 = *(volatile unsigned long long*)cntp;
    unsigned long long barBase = v0 - (v0 % (unsigned long long)GNB);
    int barK = 0;

    unsigned long long doneBase = 0;
    if (bid == 0 && tid == 0) {
        unsigned long long dv = *(volatile unsigned long long*)&g_doneCnt;
        doneBase = dv - (dv % (unsigned long long)NB);
    }

    float*  Mg  = g_M  + (size_t)grp * MAXP * MAXP;
    __half* Kg  = g_K  + (size_t)grp * MAXP * MAXP;
    __half* KTg = g_KT + (size_t)grp * MAXP * MAXP;
    float*  ug  = g_u [grp];
    float*  bvg = g_bv[grp];
    int*    permg = g_perm[grp];

    // ---------------- A0: stable permutation (per group) ----------------
    if (lb == 0) {
        int* cnt = (int*)sh;
        int base = tid * 4;
        int tv0 = T[base], tv1 = T[base+1], tv2 = T[base+2], tv3 = T[base+3];
        int c = (tv0 > 0) + (tv1 > 0) + (tv2 > 0) + (tv3 > 0);
        cnt[tid] = c;
        __syncthreads();
        for (int off = 1; off < NT; off <<= 1) {
            int vv  = cnt[tid];
            int add = (tid >= off) ? cnt[tid - off] : 0;
            __syncthreads();
            cnt[tid] = vv + add;
            __syncthreads();
        }
        int total = cnt[NT - 1];
        int excl  = cnt[tid] - c;
        int tpos = excl, cpos = total + base - excl;
        if (tv0 > 0) permg[tpos++] = base + 0; else permg[cpos++] = base + 0;
        if (tv1 > 0) permg[tpos++] = base + 1; else permg[cpos++] = base + 1;
        if (tv2 > 0) permg[tpos++] = base + 2; else permg[cpos++] = base + 2;
        if (tv3 > 0) permg[tpos++] = base + 3; else permg[cpos++] = base + 3;
        if (tid == NT - 1) { g_ntA[grp] = total; g_pA[grp] = (float)total / (float)N_; }
    }
    GBAR();

    const int   nt = g_ntA[grp];
    const int   nc = N_ - nt;
    const float p  = g_pA[grp];
    const int   R = nt + 1, C = nc + 1;
    const int   RPP = (R + 255) & ~255;
    const int   CPP = (C + 255) & ~255;
    const float a_in = p / (float)nt, a_last = 1.0f - p;
    const float b_in = (1.0f - p) / (float)nc, b_last = p;

    // ---------------- A1: gather 8 timesteps as bf16 hi/lo + fp32 squared norms ----------------
    for (int job = gw; job < SPG * N_; job += GW) {
        int s = grp * SPG + (job >> 12);
        int r = job & (N_ - 1);
        int src = permg[r];
        const float4* sp = (const float4*)(X + ((size_t)src * S_ + s) * D_);
        float4 vv = sp[lane];
        __nv_bfloat16 h0 = __float2bfloat16_rn(vv.x);
        __nv_bfloat16 h1 = __float2bfloat16_rn(vv.y);
        __nv_bfloat16 h2 = __float2bfloat16_rn(vv.z);
        __nv_bfloat16 h3 = __float2bfloat16_rn(vv.w);
        __nv_bfloat16 l0 = __float2bfloat16_rn(vv.x - __bfloat162float(h0));
        __nv_bfloat16 l1 = __float2bfloat16_rn(vv.y - __bfloat162float(h1));
        __nv_bfloat16 l2 = __float2bfloat16_rn(vv.z - __bfloat162float(h2));
        __nv_bfloat16 l3 = __float2bfloat16_rn(vv.w - __bfloat162float(h3));
        size_t off = ((size_t)s * N_ + r) * D_ + lane * 4;
        union { __nv_bfloat16 b[4]; uint2 u; } ph, pl;
        ph.b[0] = h0; ph.b[1] = h1; ph.b[2] = h2; ph.b[3] = h3;
        pl.b[0] = l0; pl.b[1] = l1; pl.b[2] = l2; pl.b[3] = l3;
        *(uint2*)(g_Xh + off) = ph.u;
        *(uint2*)(g_Xl + off) = pl.u;
        float sq = vv.x*vv.x + vv.y*vv.y + vv.z*vv.z + vv.w*vv.w;
        sq = warpSumF(sq);
        if (lane == 0) g_nrm[s * N_ + r] = sq;
    }
    GBAR();

    // ================== per-timestep loop ==================
    for (int sl = 0; sl < SPG; sl++) {
        const int s = grp * SPG + sl;
        const float* nrm = g_nrm + s * N_;
        const __nv_bfloat16* Xhs = g_Xh + (size_t)s * N_ * D_;
        const __nv_bfloat16* Xls = g_Xl + (size_t)s * N_ * D_;

        // ---------- B1: M = nx + ny - 2*(hi.hi + hi.lo + lo.hi) via mma.sync ----------
        {
            const int tilesI = (nt + 127) >> 7;
            const int tilesJ = (nc + 127) >> 7;
            const int nTiles = tilesI * tilesJ;
            const int wm = wid >> 2;          // 0..7 : m-offset wm*16
            const int wn = wid & 3;           // 0..3 : n-offset wn*32
            const int ldrow = tid >> 3;       // 0..127 : load row
            const int ldch  = tid & 7;        // 0..7  : 16B chunk
            float  lmax = -FLT_MAX;
            double lsum = 0.0;

            for (int tile = lb; tile < nTiles; tile += GNB) {
                int ti = tile / tilesJ, tj = tile - ti * tilesJ;
                int i0 = ti << 7, j0 = tj << 7;

                float acc[4][4];
                #pragma unroll
                for (int q = 0; q < 4; q++)
                    #pragma unroll
                    for (int c = 0; c < 4; c++) acc[q][c] = 0.0f;

                for (int kb = 0; kb < D_; kb += 64) {
                    __syncthreads();
                    {   // load 4 tiles: 1 uint4 each per thread, 144B padded rows
                        int ar = i0 + ldrow; if (ar >= nt) ar = nt - 1;
                        int br = j0 + ldrow; if (br >= nc) br = nc - 1;
                        size_t aoff = ((size_t)ar) * D_ + kb + ldch * 8;
                        size_t boff = ((size_t)(nt + br)) * D_ + kb + ldch * 8;
                        uint4 vah = *(const uint4*)(Xhs + aoff);
                        uint4 val = *(const uint4*)(Xls + aoff);
                        uint4 vbh = *(const uint4*)(Xhs + boff);
                        uint4 vbl = *(const uint4*)(Xls + boff);
                        int sm = ldrow * LDH + ldch * 8;
                        *(uint4*)&Ah[sm] = vah;
                        *(uint4*)&Al[sm] = val;
                        *(uint4*)&Bh[sm] = vbh;
                        *(uint4*)&Bl[sm] = vbl;
                    }
                    __syncthreads();
                    #pragma unroll
                    for (int ks = 0; ks < 4; ks++) {
                        const int k0 = ks * 16;
                        const int arow = wm * 16 + (lane >> 2);
                        const int ac   = k0 + (lane & 3) * 2;
                        unsigned ah0 = *(const unsigned*)&Ah[arow * LDH + ac];
                        unsigned ah1 = *(const unsigned*)&Ah[(arow + 8) * LDH + ac];
                        unsigned ah2 = *(const unsigned*)&Ah[arow * LDH + ac + 8];
                        unsigned ah3 = *(const unsigned*)&Ah[(arow + 8) * LDH + ac + 8];
                        unsigned al0 = *(const unsigned*)&Al[arow * LDH + ac];
                        unsigned al1 = *(const unsigned*)&Al[(arow + 8) * LDH + ac];
                        unsigned al2 = *(const unsigned*)&Al[arow * LDH + ac + 8];
                        unsigned al3 = *(const unsigned*)&Al[(arow + 8) * LDH + ac + 8];
                        #pragma unroll
                        for (int q = 0; q < 4; q++) {
                            const int bn = wn * 32 + q * 8 + (lane >> 2);
                            unsigned bh0 = *(const unsigned*)&Bh[bn * LDH + ac];
                            unsigned bh1 = *(const unsigned*)&Bh[bn * LDH + ac + 8];
                            unsigned bl0 = *(const unsigned*)&Bl[bn * LDH + ac];
                            unsigned bl1 = *(const unsigned*)&Bl[bn * LDH + ac + 8];
                            mma16816(acc[q][0], acc[q][1], acc[q][2], acc[q][3],
                                     ah0, ah1, ah2, ah3, bh0, bh1);
                            mma16816(acc[q][0], acc[q][1], acc[q][2], acc[q][3],
                                     ah0, ah1, ah2, ah3, bl0, bl1);
                            mma16816(acc[q][0], acc[q][1], acc[q][2], acc[q][3],
                                     al0, al1, al2, al3, bh0, bh1);
                        }
                    }
                }

                // epilogue: M = nx + ny - 2*dot; track max + sum
                float tsum = 0.0f;
                const int er0 = i0 + wm * 16 + (lane >> 2);
                #pragma unroll
                for (int half = 0; half < 2; half++) {
                    const int rr = er0 + half * 8;
                    if (rr >= nt) continue;
                    const float nx = nrm[rr];
                    float* Mrow = Mg + (size_t)rr * CPP;
                    #pragma unroll
                    for (int q = 0; q < 4; q++) {
                        const int cc = j0 + wn * 32 + q * 8 + (lane & 3) * 2;
                        const float d0 = acc[q][half * 2 + 0];
                        const float d1 = acc[q][half * 2 + 1];
                        if (cc + 1 < nc) {
                            float m0 = fmaf(-2.0f, d0, nx + nrm[nt + cc]);
                            float m1 = fmaf(-2.0f, d1, nx + nrm[nt + cc + 1]);
                            *(float2*)(Mrow + cc) = make_float2(m0, m1);
                            lmax = fmaxf(lmax, fmaxf(m0, m1));
                            tsum += m0 + m1;
                        } else if (cc < nc) {
                            float m0 = fmaf(-2.0f, d0, nx + nrm[nt + cc]);
                            Mrow[cc] = m0;
                            lmax = fmaxf(lmax, m0);
                            tsum += m0;
                        }
                    }
                }
                lsum += (double)tsum;
            }
            lmax = warpMaxF(lmax);
            lsum = warpSumD(lsum);
            __syncthreads();
            if (lane == 0) { s_f[wid] = lmax; s_d[wid] = lsum; }
            __syncthreads();
            if (wid == 0) {
                float  m2 = s_f[lane];
                double s2 = s_d[lane];
                m2 = warpMaxF(m2);
                s2 = warpSumD(s2);
                if (lane == 0) { g_pmax[grp][lb] = m2; g_psum[grp][lb] = s2; }
            }
        }
        GBAR();

        // ---------- B2: reduce GNB partials (identical fixed order in every block) ----------
        if (tid == 0) {
            float  dmax = -FLT_MAX;
            double dsum = 0.0;
            #pragma unroll 6
            for (int k2 = 0; k2 < GNB; k2++) {
                dmax = fmaxf(dmax, __ldcg(&g_pmax[grp][k2]));
                dsum += __ldcg(&g_psum[grp][k2]);
            }
            s_delta  = dmax;
            s_efflam = (float)(((double)nt * (double)nc) / dsum);
        }
        __syncthreads();
        const float delta  = s_delta;
        const float efflam = s_efflam;

        // ---------- B3: K = exp(-efflam*Mt)+eps (fp16, segment-permuted), K^T transpose ----------
        {
            const int rowStrips = RPP >> 5, colStrips = CPP >> 7;
            const int nStr = rowStrips * colStrips;
            const int srow = wid;
            const int tj = tid >> 3;
            const int io = (tid & 7) * 4;
            const float kdelta = fast_exp(-efflam * delta) + EPSK;

            for (int str = lb; str < nStr; str += GNB) {
                int sr = str / colStrips, sc = str - sr * colStrips;
                int i0 = sr << 5, j0 = sc << 7;
                int i = i0 + srow;
                float kq[4];
                #pragma unroll
                for (int q = 0; q < 4; q++) {
                    int j = j0 + lane * 4 + q;
                    float kv;
                    if (i < nt && j < nc) {
                        float m = __ldcg(&Mg[(size_t)i * CPP + j]);
                        kv = fast_exp(-efflam * m) + EPSK;
                    } else if (i == nt && j < nc) kv = kdelta;
                    else if (j == nc && i < nt)   kv = kdelta;
                    else if (i == nt && j == nc)  kv = 1.0f + EPSK;
                    else                          kv = 0.0f;
                    kq[q] = kv;
                }
                *(float4*)&sh[srow * 132 + lane * 4] = make_float4(kq[0], kq[1], kq[2], kq[3]);
                {
                    union { __half2 h[2]; uint2 u; } cv;
                    cv.h[0] = __floats2half2_rn(kq[0], kq[1]);
                    cv.h[1] = __floats2half2_rn(kq[2], kq[3]);
                    int halfOff = (j0 & ~255) + lane * 8 + ((j0 & 128) ? 4 : 0);
                    *(uint2*)&Kg[(size_t)i * CPP + halfOff] = cv.u;
                }
                __syncthreads();
                {
                    union { __half2 h[2]; uint2 u; } cv;
                    cv.h[0] = __floats2half2_rn(sh[(io+0)*132 + tj], sh[(io+1)*132 + tj]);
                    cv.h[1] = __floats2half2_rn(sh[(io+2)*132 + tj], sh[(io+3)*132 + tj]);
                    int ii = i0 + io;
                    int halfOff = (ii & ~255) + ((ii & 127) >> 2) * 8 + ((ii & 128) ? 4 : 0);
                    *(uint2*)&KTg[(size_t)(j0 + tj) * RPP + halfOff] = cv.u;
                }
                __syncthreads();
            }
            if (lb == 0) {
                for (int r2 = tid; r2 < RPP; r2 += NT)
                    ug[r2] = (r2 < nt) ? a_in : ((r2 == nt) ? a_last : 0.0f);
                for (int c2 = tid; c2 < CPP; c2 += NT)
                    if (c2 >= C) bvg[c2] = 0.0f;
            }
        }
        GBAR();

        // ---------- Sinkhorn: 20 iterations + final v pass (4 rows/warp, MLP=4) ----------
        const int segU = RPP >> 8;
        const int segB = CPP >> 8;
        const float4* ug4  = (const float4*)ug;
        const float4* bvg4 = (const float4*)bvg;
        const int cb4 = jid * 4;   // pass1 columns
        const int rb4 = jid * 4;   // pass2 rows

        for (int it = 0; it <= ITS; it++) {
            // pass1: bv = b / (K^T u)
            for (int i4 = tid; i4 < (RPP >> 2); i4 += NT)
                ((float4*)sh)[i4] = __ldcg(ug4 + i4);
            __syncthreads();
            if (cb4 < C) {    // padded KT rows beyond C are valid zeros; reads unguarded
                float s0, s1, s2, s3;
                dot4rows(KTg, RPP, cb4, sh, segU, lane, s0, s1, s2, s3);
                if (lane == 0) {
                    bvg[cb4] = ((cb4 < nc) ? b_in : b_last) / s0;
                    if (cb4 + 1 < C) bvg[cb4 + 1] = ((cb4 + 1 < nc) ? b_in : b_last) / s1;
                    if (cb4 + 2 < C) bvg[cb4 + 2] = ((cb4 + 2 < nc) ? b_in : b_last) / s2;
                    if (cb4 + 3 < C) bvg[cb4 + 3] = ((cb4 + 3 < nc) ? b_in : b_last) / s3;
                }
            }
            GBAR();
            if (it == ITS) break;

            // pass2: u = a / (K bv)
            for (int i4 = tid; i4 < (CPP >> 2); i4 += NT)
                ((float4*)sh)[i4] = __ldcg(bvg4 + i4);
            __syncthreads();
            if (rb4 < R) {
                float s0, s1, s2, s3;
                dot4rows(Kg, CPP, rb4, sh, segB, lane, s0, s1, s2, s3);
                if (lane == 0) {
                    ug[rb4] = ((rb4 < nt) ? a_in : a_last) / s0;
                    if (rb4 + 1 < R) ug[rb4 + 1] = ((rb4 + 1 < nt) ? a_in : a_last) / s1;
                    if (rb4 + 2 < R) ug[rb4 + 2] = ((rb4 + 2 < nt) ? a_in : a_last) / s2;
                    if (rb4 + 3 < R) ug[rb4 + 3] = ((rb4 + 3 < nt) ? a_in : a_last) / s3;
                }
            }
            GBAR();
        }

        // ---------- Final: 2 * sum u_i K_ij v_j Mt_ij ----------
        {
            for (int i4 = tid; i4 < (CPP >> 2); i4 += NT)
                ((float4*)sh)[i4] = __ldcg(bvg4 + i4);
            __syncthreads();
            double wacc = 0.0;
            for (int r2 = gw; r2 < R; r2 += GW) {
                const uint4*  Kr = (const uint4*)(Kg + (size_t)r2 * CPP);
                const float4* Mr = (const float4*)(Mg + (size_t)r2 * CPP);
                const bool lastRow = (r2 == nt);
                float acc = 0.0f;
                for (int sg = 0; sg < segB; sg++) {
                    uint4 kv = __ldcg(Kr + sg * 32 + lane);
                    const __half2* hp = (const __half2*)&kv;
                    float4 m0 = __ldcg(Mr + sg * 64 + lane);
                    float4 m1 = __ldcg(Mr + sg * 64 + 32 + lane);
                    float4 vv0 = *(const float4*)&sh[sg * 256 + lane * 4];
                    float4 vv1 = *(const float4*)&sh[sg * 256 + 128 + lane * 4];
                    float2 f0 = __half22float2(hp[0]);
                    float2 f1 = __half22float2(hp[1]);
                    float2 f2 = __half22float2(hp[2]);
                    float2 f3 = __half22float2(hp[3]);
                    int j1 = sg * 256 + lane * 4;
                    int j2 = j1 + 128;
                    float mt[8];
                    if (lastRow) {
                        mt[0] = (j1+0 < nc) ? delta : 0.0f;
                        mt[1] = (j1+1 < nc) ? delta : 0.0f;
                        mt[2] = (j1+2 < nc) ? delta : 0.0f;
                        mt[3] = (j1+3 < nc) ? delta : 0.0f;
                        mt[4] = (j2+0 < nc) ? delta : 0.0f;
                        mt[5] = (j2+1 < nc) ? delta : 0.0f;
                        mt[6] = (j2+2 < nc) ? delta : 0.0f;
                        mt[7] = (j2+3 < nc) ? delta : 0.0f;
                    } else {
                        mt[0] = (j1+0 < nc) ? m0.x : ((j1+0 == nc) ? delta : 0.0f);
                        mt[1] = (j1+1 < nc) ? m0.y : ((j1+1 == nc) ? delta : 0.0f);
                        mt[2] = (j1+2 < nc) ? m0.z : ((j1+2 == nc) ? delta : 0.0f);
                        mt[3] = (j1+3 < nc) ? m0.w : ((j1+3 == nc) ? delta : 0.0f);
                        mt[4] = (j2+0 < nc) ? m1.x : ((j2+0 == nc) ? delta : 0.0f);
                        mt[5] = (j2+1 < nc) ? m1.y : ((j2+1 == nc) ? delta : 0.0f);
                        mt[6] = (j2+2 < nc) ? m1.z : ((j2+2 == nc) ? delta : 0.0f);
                        mt[7] = (j2+3 < nc) ? m1.w : ((j2+3 == nc) ? delta : 0.0f);
                    }
                    acc = fmaf(f0.x * vv0.x, mt[0], acc);
                    acc = fmaf(f0.y * vv0.y, mt[1], acc);
                    acc = fmaf(f1.x * vv0.z, mt[2], acc);
                    acc = fmaf(f1.y * vv0.w, mt[3], acc);
                    acc = fmaf(f2.x * vv1.x, mt[4], acc);
                    acc = fmaf(f2.y * vv1.y, mt[5], acc);
                    acc = fmaf(f3.x * vv1.z, mt[6], acc);
                    acc = fmaf(f3.y * vv1.w, mt[7], acc);
                }
                acc = warpSumF(acc);
                if (lane == 0) wacc += (double)(__ldcg(&ug[r2]) * acc);
            }
            __syncthreads();
            if (lane == 0) s_d[wid] = wacc;
            __syncthreads();
            if (wid == 0) {
                double t2 = warpSumD(s_d[lane]);
                if (lane == 0) g_pres[grp][lb] = t2;
            }
        }
        GBAR();
        if (lb == 0 && tid == 0) {
            double ts = 0.0;
            #pragma unroll 6
            for (int k2 = 0; k2 < GNB; k2++) ts += __ldcg(&g_pres[grp][k2]);
            g_res[s] = 2.0 * ts;
        }
    }

    // ---------------- global combine ----------------
    __threadfence();
    __syncthreads();
    if (tid == 0) atomicAdd(&g_doneCnt, 1ULL);
    if (bid == 0 && tid == 0) {
        unsigned long long tgt = doneBase + (unsigned long long)NB;
        while (*(volatile unsigned long long*)&g_doneCnt < tgt) { __nanosleep(128); }
        __threadfence();
        double total = 0.0;
        for (int s = 0; s < S_; s++) total += __ldcg(&g_res[s]);
        out[0] = (float)total;
    }
}

extern "C" void kernel_launch(void* const* d_in, const int* in_sizes, int n_in,
                              void* d_out, int out_size) {
    const float* X = (const float*)d_in[0];
    const int*   T = (const int*)d_in[1];
    float* out = (float*)d_out;
    (void)in_sizes; (void)n_in; (void)out_size;
    cudaFuncSetAttribute(sinkhorn_all, cudaFuncAttributeMaxDynamicSharedMemorySize, SMEM_BYTES);
    sinkhorn_all<<<NB, NT, SMEM_BYTES>>>(X, T, out);
}